// round 2
// baseline (speedup 1.0000x reference)
#include <cuda_runtime.h>
#include <cuda_bf16.h>
#include <cstdint>

#define B_ 512
#define D_ 256
#define P_ 196
#define N2 1024   // 2*B

// ---------------- device scratch (no allocations allowed) ----------------
__device__ float g_Z[(size_t)P_ * N2 * D_];   // [p][row][d]; rows 0..511 = A (local), 512..1023 = G chain
__device__ float g_S[P_ * N2];                // per-row sums of exp(sim)
__device__ float g_rn2[P_ * N2];              // per-row |z|^2 (diag correction)
__device__ float g_wt[P_];                    // raw attention sums per position
__device__ float g_dsum[P_];                  // sum_i A_i . G_i per position
__device__ float g_ploss[P_];                 // per-position loss

// ---------------- fast exp2 on the FMA pipe (avoid MUFU) ----------------
__device__ __forceinline__ float fast_exp2(float y) {
    float nf = rintf(y);
    float f  = y - nf;
    float r  = 1.3333558e-3f;
    r = fmaf(r, f, 9.6181291e-3f);
    r = fmaf(r, f, 5.5504109e-2f);
    r = fmaf(r, f, 2.4022651e-1f);
    r = fmaf(r, f, 6.9314718e-1f);
    r = fmaf(r, f, 1.0f);
    int n = (int)nf;
    return __int_as_float(__float_as_int(r) + (n << 23));
}
__device__ __forceinline__ float fast_exp(float x) { return fast_exp2(x * 1.442695041f); }

// exp(dot / T) with T=0.5 -> exp2(dot * 2*log2(e))
#define EXP_SCALE 2.8853900817779268f

// ---------------- block reductions (256 threads) ----------------
__device__ __forceinline__ float warpSum(float v) {
    #pragma unroll
    for (int o = 16; o > 0; o >>= 1) v += __shfl_xor_sync(0xffffffffu, v, o);
    return v;
}
__device__ __forceinline__ float warpMax(float v) {
    #pragma unroll
    for (int o = 16; o > 0; o >>= 1) v = fmaxf(v, __shfl_xor_sync(0xffffffffu, v, o));
    return v;
}
__device__ __forceinline__ float blockSum256(float v, float* sh) {
    int w = threadIdx.x >> 5, l = threadIdx.x & 31;
    v = warpSum(v);
    __syncthreads();
    if (l == 0) sh[w] = v;
    __syncthreads();
    if (w == 0) {
        float x = (l < 8) ? sh[l] : 0.0f;
        x = warpSum(x);
        if (l == 0) sh[0] = x;
    }
    __syncthreads();
    return sh[0];
}
__device__ __forceinline__ float blockMax256(float v, float* sh) {
    int w = threadIdx.x >> 5, l = threadIdx.x & 31;
    v = warpMax(v);
    __syncthreads();
    if (l == 0) sh[w] = v;
    __syncthreads();
    if (w == 0) {
        float x = (l < 8) ? sh[l] : -3.4e38f;
        x = warpMax(x);
        if (l == 0) sh[0] = x;
    }
    __syncthreads();
    return sh[0];
}

// ---------------- f32x2 packed helpers ----------------
__device__ __forceinline__ unsigned s2u(const void* p) {
    return (unsigned)__cvta_generic_to_shared(p);
}
__device__ __forceinline__ unsigned long long splat2(float v) {
    unsigned long long r; unsigned u = __float_as_uint(v);
    asm("mov.b64 %0, {%1, %2};" : "=l"(r) : "r"(u), "r"(u));
    return r;
}
__device__ __forceinline__ float2 unpack2(unsigned long long v) {
    unsigned lo, hi;
    asm("mov.b64 {%0, %1}, %2;" : "=r"(lo), "=r"(hi) : "l"(v));
    return make_float2(__uint_as_float(lo), __uint_as_float(hi));
}
#define LDSV2(r0_, r1_, addr_) \
    asm volatile("ld.shared.v2.u64 {%0, %1}, [%2];" : "=l"(r0_), "=l"(r1_) : "r"(addr_))
#define FMA2(c_, a_, b_) \
    asm("fma.rn.f32x2 %0, %1, %2, %0;" : "+l"(c_) : "l"(a_), "l"(b_))

// ---------------- stage 1: global-feature softmax chain ----------------
__global__ __launch_bounds__(256) void k_buildG(const float* __restrict__ gf) {
    int b = blockIdx.x;
    int d = threadIdx.x;
    __shared__ float sh[32];
    float v = gf[b * D_ + d];
    for (int p = 0; p < P_; p++) {
        float m = blockMax256(v, sh);
        float e = fast_exp(v - m);
        float s = blockSum256(e, sh);
        v = e * (1.0f / s);                        // carry: softmax output
        float q = blockSum256(v * v, sh);
        float inv = 1.0f / (sqrtf(q) + 1e-8f);
        g_Z[((size_t)p * N2 + B_ + b) * D_ + d] = v * inv;
        if (d == 0) g_rn2[p * N2 + B_ + b] = q * inv * inv;
    }
}

// ---------------- stage 2: local-feature softmax + normalize ----------------
__global__ __launch_bounds__(256) void k_buildA(const float* __restrict__ outp) {
    int p = blockIdx.x;
    int b = blockIdx.y;
    int d = threadIdx.x;
    __shared__ float sh[32];
    float x = outp[((size_t)b * D_ + d) * P_ + p];
    float m = blockMax256(x, sh);
    float e = fast_exp(x - m);
    float s = blockSum256(e, sh);
    float v = e * (1.0f / s);
    float q = blockSum256(v * v, sh);
    float inv = 1.0f / (sqrtf(q) + 1e-8f);
    g_Z[((size_t)p * N2 + b) * D_ + d] = v * inv;
    if (d == 0) g_rn2[p * N2 + b] = q * inv * inv;
}

// ---------------- attention weights ----------------
__global__ __launch_bounds__(256) void k_wt(const float* __restrict__ att) {
    int p = blockIdx.x;
    __shared__ float sh[32];
    float s = 0.0f;
    for (int bc = threadIdx.x; bc < B_ * 8; bc += 256) s += att[(size_t)bc * P_ + p];
    s = blockSum256(s, sh);
    if (threadIdx.x == 0) g_wt[p] = s;
}

// ---------------- positive-pair dots: dsum[p] = sum_i A_i . G_i ----------------
__global__ __launch_bounds__(256) void k_dsum() {
    int p = blockIdx.x;
    int w = threadIdx.x >> 5, l = threadIdx.x & 31;
    __shared__ float sh[32];
    float part = 0.0f;
    for (int i = w; i < B_; i += 8) {
        const float4* a4 = (const float4*)(g_Z + ((size_t)p * N2 + i) * D_);
        const float4* g4 = (const float4*)(g_Z + ((size_t)p * N2 + B_ + i) * D_);
        float4 av = a4[l * 2], gv = g4[l * 2];
        part += av.x * gv.x + av.y * gv.y + av.z * gv.z + av.w * gv.w;
        av = a4[l * 2 + 1]; gv = g4[l * 2 + 1];
        part += av.x * gv.x + av.y * gv.y + av.z * gv.z + av.w * gv.w;
    }
    part = blockSum256(part, sh);
    if (threadIdx.x == 0) g_dsum[p] = part;
}

// ---------------- main: per-position 1024x1024x256 GEMM + exp + rowsum -------
// Block = 128 rows x all 1024 cols (8 col tiles), 256 threads, 8x8 micro-tile,
// fma.rn.f32x2 packed pairs along columns. Row sums of exp never leave regs.
__global__ __launch_bounds__(256, 2) void k_main() {
    int p  = blockIdx.y;
    int r0 = blockIdx.x << 7;
    const float* Zp = g_Z + (size_t)p * (N2 * D_);

    __shared__ unsigned long long As2[16][128];  // splatted row operand [k][row]
    __shared__ float Bs[16][128];                // col operand [k][col]

    int tid  = threadIdx.x;
    int tx   = tid & 15, ty = tid >> 4;
    int lrow = tid >> 1;
    int lk   = (tid & 1) << 3;

    const float* gA = Zp + (size_t)(r0 + lrow) * D_ + lk;

    float rowS[8];
    #pragma unroll
    for (int i = 0; i < 8; i++) rowS[i] = 0.0f;

    unsigned aRd = s2u(&As2[0][0]) + ty * 64;   // ty*8 u64 slots
    unsigned bRd = s2u(&Bs[0][0]) + tx * 32;    // tx*8 floats

    #pragma unroll 1
    for (int ct = 0; ct < 8; ct++) {
        const float* gB = Zp + (size_t)((ct << 7) + lrow) * D_ + lk;
        unsigned long long acc[8][4];
        #pragma unroll
        for (int i = 0; i < 8; i++)
            #pragma unroll
            for (int j = 0; j < 4; j++) acc[i][j] = 0ull;

        float4 pa0 = *(const float4*)(gA);
        float4 pa1 = *(const float4*)(gA + 4);
        float4 pb0 = *(const float4*)(gB);
        float4 pb1 = *(const float4*)(gB + 4);

        #pragma unroll 1
        for (int kc = 0; kc < 256; kc += 16) {
            __syncthreads();
            As2[lk + 0][lrow] = splat2(pa0.x);
            As2[lk + 1][lrow] = splat2(pa0.y);
            As2[lk + 2][lrow] = splat2(pa0.z);
            As2[lk + 3][lrow] = splat2(pa0.w);
            As2[lk + 4][lrow] = splat2(pa1.x);
            As2[lk + 5][lrow] = splat2(pa1.y);
            As2[lk + 6][lrow] = splat2(pa1.z);
            As2[lk + 7][lrow] = splat2(pa1.w);
            Bs[lk + 0][lrow] = pb0.x;
            Bs[lk + 1][lrow] = pb0.y;
            Bs[lk + 2][lrow] = pb0.z;
            Bs[lk + 3][lrow] = pb0.w;
            Bs[lk + 4][lrow] = pb1.x;
            Bs[lk + 5][lrow] = pb1.y;
            Bs[lk + 6][lrow] = pb1.z;
            Bs[lk + 7][lrow] = pb1.w;
            __syncthreads();
            if (kc < 240) {   // prefetch next k-chunk during compute
                pa0 = *(const float4*)(gA + kc + 16);
                pa1 = *(const float4*)(gA + kc + 20);
                pb0 = *(const float4*)(gB + kc + 16);
                pb1 = *(const float4*)(gB + kc + 20);
            }
            #pragma unroll
            for (int kk = 0; kk < 16; kk++) {
                unsigned long long a2[8], b2[4];
                unsigned ao = aRd + kk * 1024;
                unsigned bo = bRd + kk * 512;
                LDSV2(a2[0], a2[1], ao);
                LDSV2(a2[2], a2[3], ao + 16);
                LDSV2(a2[4], a2[5], ao + 32);
                LDSV2(a2[6], a2[7], ao + 48);
                LDSV2(b2[0], b2[1], bo);
                LDSV2(b2[2], b2[3], bo + 16);
                #pragma unroll
                for (int i = 0; i < 8; i++)
                    #pragma unroll
                    for (int j = 0; j < 4; j++)
                        FMA2(acc[i][j], a2[i], b2[j]);
            }
        }
        // epilogue: exp(sim) and accumulate row sums (registers only)
        #pragma unroll
        for (int i = 0; i < 8; i++) {
            float s = 0.0f;
            #pragma unroll
            for (int j = 0; j < 4; j++) {
                float2 v = unpack2(acc[i][j]);
                s += fast_exp2(v.x * EXP_SCALE);
                s += fast_exp2(v.y * EXP_SCALE);
            }
            rowS[i] += s;
        }
    }

    // cross-thread row-sum reduction (16 tx partials per row)
    __syncthreads();
    float* red = (float*)&As2[0][0];   // 4096 floats of smem available
    #pragma unroll
    for (int i = 0; i < 8; i++) red[tx * 128 + ty * 8 + i] = rowS[i];
    __syncthreads();
    if (tid < 128) {
        float s = 0.0f;
        #pragma unroll
        for (int t = 0; t < 16; t++) s += red[t * 128 + tid];
        g_S[p * N2 + r0 + tid] = s;
    }
}

// ---------------- per-position loss ----------------
__global__ __launch_bounds__(256) void k_final() {
    int p = blockIdx.x;
    __shared__ float sh[32];
    float acc = 0.0f;
    for (int r = threadIdx.x; r < N2; r += 256) {
        float self = fast_exp2(g_rn2[p * N2 + r] * EXP_SCALE);   // exp(sim_rr)
        acc += logf(g_S[p * N2 + r] - self);
    }
    acc = blockSum256(acc, sh);
    if (threadIdx.x == 0) {
        // loss_p = [(sum_r log S'_r - 4*dsum) / (2B)] * (wt_raw/B) / P
        g_ploss[p] = (acc - 4.0f * g_dsum[p]) * g_wt[p] *
                     (1.0f / ((float)N2 * (float)B_ * (float)P_));
    }
}

// ---------------- final scalar ----------------
__global__ __launch_bounds__(256) void k_out(float* out, int n) {
    __shared__ float sh[32];
    int t = threadIdx.x;
    for (int i = t; i < n; i += 256) out[i] = 0.0f;
    float v = (t < P_) ? g_ploss[t] : 0.0f;
    v = blockSum256(v, sh);
    if (t == 0) out[0] = v;
}

// ---------------- launch ----------------
extern "C" void kernel_launch(void* const* d_in, const int* in_sizes, int n_in,
                              void* d_out, int out_size) {
    const float* gf = nullptr; const float* att = nullptr; const float* outp = nullptr;
    for (int i = 0; i < n_in; i++) {
        if (in_sizes[i] == B_ * D_)            gf   = (const float*)d_in[i];
        else if (in_sizes[i] == B_ * 8 * P_)   att  = (const float*)d_in[i];
        else if (in_sizes[i] == B_ * D_ * P_)  outp = (const float*)d_in[i];
    }
    if (!gf)   gf   = (const float*)d_in[0];
    if (!att)  att  = (const float*)d_in[1];
    if (!outp) outp = (const float*)d_in[2];

    k_buildG<<<B_, 256>>>(gf);
    k_buildA<<<dim3(P_, B_), 256>>>(outp);
    k_wt<<<P_, 256>>>(att);
    k_dsum<<<P_, 256>>>();
    k_main<<<dim3(8, P_), 256>>>();
    k_final<<<P_, 256>>>();
    k_out<<<1, 256>>>((float*)d_out, out_size);
}

// round 4
// speedup vs baseline: 4.4123x; 4.4123x over previous
#include <cuda_runtime.h>
#include <cuda_bf16.h>
#include <cstdint>

#define B_ 512
#define D_ 256
#define P_ 196
#define N2 1024   // 2*B

// exp(dot / T) with T=0.5 -> exp2(dot * 2*log2(e))
#define EXP_SCALE 2.8853900817779268f
#define LOG2E     1.4426950408889634f

// ---------------- device scratch (no allocations allowed) ----------------
__device__ __nv_bfloat16 g_Zh[(size_t)P_ * N2 * D_];  // [p][row][d] bf16; rows 0..511 local, 512..1023 G chain
__device__ float g_S[P_ * N2];      // per-row sums of exp(sim)
__device__ float g_rn2[P_ * N2];    // per-row |z|^2 (diag correction)
__device__ float g_wt[P_];          // raw attention sums per position
__device__ float g_dsum4[P_ * 4];   // partial positive-pair dots (per row-tile rt<4)
__device__ float g_ploss[P_];       // per-position loss

// ---------------- small helpers ----------------
__device__ __forceinline__ float ex2f(float x) {
    float y; asm("ex2.approx.f32 %0, %1;" : "=f"(y) : "f"(x)); return y;
}
__device__ __forceinline__ unsigned s2u(const void* p) {
    return (unsigned)__cvta_generic_to_shared(p);
}
__device__ __forceinline__ float warpSum(float v) {
    #pragma unroll
    for (int o = 16; o > 0; o >>= 1) v += __shfl_xor_sync(0xffffffffu, v, o);
    return v;
}
__device__ __forceinline__ float warpMax(float v) {
    #pragma unroll
    for (int o = 16; o > 0; o >>= 1) v = fmaxf(v, __shfl_xor_sync(0xffffffffu, v, o));
    return v;
}
__device__ __forceinline__ float blockSum256(float v, float* sh) {
    int w = threadIdx.x >> 5, l = threadIdx.x & 31;
    v = warpSum(v);
    __syncthreads();
    if (l == 0) sh[w] = v;
    __syncthreads();
    if (w == 0) {
        float x = (l < 8) ? sh[l] : 0.0f;
        x = warpSum(x);
        if (l == 0) sh[0] = x;
    }
    __syncthreads();
    return sh[0];
}

#define CPA16(dst_, src_) \
    asm volatile("cp.async.cg.shared.global [%0], [%1], 16;" :: "r"(dst_), "l"(src_))
#define CPA_COMMIT() asm volatile("cp.async.commit_group;" ::: "memory")
#define CPA_WAIT1()  asm volatile("cp.async.wait_group 1;"  ::: "memory")

#define LDSM4(r0_, r1_, r2_, r3_, addr_) \
    asm volatile("ldmatrix.sync.aligned.m8n8.x4.shared.b16 {%0,%1,%2,%3}, [%4];" \
        : "=r"(r0_), "=r"(r1_), "=r"(r2_), "=r"(r3_) : "r"(addr_))

#define MMA16816(c_, a_, b0_, b1_) \
    asm volatile("mma.sync.aligned.m16n8k16.row.col.f32.bf16.bf16.f32 " \
        "{%0,%1,%2,%3}, {%4,%5,%6,%7}, {%8,%9}, {%0,%1,%2,%3};" \
        : "+f"((c_)[0]), "+f"((c_)[1]), "+f"((c_)[2]), "+f"((c_)[3]) \
        : "r"((a_)[0]), "r"((a_)[1]), "r"((a_)[2]), "r"((a_)[3]), "r"(b0_), "r"(b1_))

// ---------------- stage 1: global-feature softmax chain (1 warp / row) ------
__global__ __launch_bounds__(32) void k_buildG(const float* __restrict__ gf) {
    int b = blockIdx.x;
    int lane = threadIdx.x;
    float v[8];
    #pragma unroll
    for (int j = 0; j < 8; j++) v[j] = gf[b * D_ + j * 32 + lane];
    for (int p = 0; p < P_; p++) {
        float m = v[0];
        #pragma unroll
        for (int j = 1; j < 8; j++) m = fmaxf(m, v[j]);
        m = warpMax(m);
        float e[8], s = 0.0f, s2 = 0.0f;
        #pragma unroll
        for (int j = 0; j < 8; j++) {
            e[j] = ex2f((v[j] - m) * LOG2E);
            s  += e[j];
            s2 += e[j] * e[j];
        }
        s  = warpSum(s);
        s2 = warpSum(s2);
        float inv_s = 1.0f / s;
        float q = s2 * inv_s * inv_s;               // |softmax|^2
        float inv = 1.0f / (sqrtf(q) + 1e-8f);
        float sc = inv_s * inv;
        #pragma unroll
        for (int j = 0; j < 8; j++) {
            g_Zh[((size_t)p * N2 + B_ + b) * D_ + j * 32 + lane] =
                __float2bfloat16(e[j] * sc);
            v[j] = e[j] * inv_s;                    // carry softmax output
        }
        if (lane == 0) g_rn2[p * N2 + B_ + b] = q * inv * inv;
    }
}

// ---------------- stage 2: local-feature softmax (coalesced, 32 p per block)
__global__ __launch_bounds__(256) void k_buildA(const float* __restrict__ outp) {
    __shared__ float tile[32 * 264];     // [p_local][d] stride 264
    int pg = blockIdx.x, b = blockIdx.y;
    int tid = threadIdx.x;
    // coalesced load: p fastest
    #pragma unroll 4
    for (int i = 0; i < 32; i++) {
        int idx = tid + (i << 8);
        int pl = idx & 31, d = idx >> 5;
        int p = pg * 32 + pl;
        float x = (p < P_) ? outp[((size_t)b * D_ + d) * P_ + p] : 0.0f;
        tile[pl * 264 + d] = x;
    }
    __syncthreads();
    int dg = tid & 7, pl = tid >> 3;
    int p  = pg * 32 + pl;
    float x[32];
    #pragma unroll
    for (int j = 0; j < 32; j++) x[j] = tile[pl * 264 + dg + 8 * j];
    float m = x[0];
    #pragma unroll
    for (int j = 1; j < 32; j++) m = fmaxf(m, x[j]);
    m = fmaxf(m, __shfl_xor_sync(~0u, m, 1));
    m = fmaxf(m, __shfl_xor_sync(~0u, m, 2));
    m = fmaxf(m, __shfl_xor_sync(~0u, m, 4));
    float e[32], s = 0.0f, s2 = 0.0f;
    #pragma unroll
    for (int j = 0; j < 32; j++) {
        e[j] = ex2f((x[j] - m) * LOG2E);
        s += e[j]; s2 += e[j] * e[j];
    }
    s  += __shfl_xor_sync(~0u, s, 1);  s  += __shfl_xor_sync(~0u, s, 2);  s  += __shfl_xor_sync(~0u, s, 4);
    s2 += __shfl_xor_sync(~0u, s2, 1); s2 += __shfl_xor_sync(~0u, s2, 2); s2 += __shfl_xor_sync(~0u, s2, 4);
    float inv_s = 1.0f / s;
    float q = s2 * inv_s * inv_s;
    float inv = 1.0f / (sqrtf(q) + 1e-8f);
    float sc = inv_s * inv;
    if (dg == 0 && p < P_) g_rn2[p * N2 + b] = q * inv * inv;
    __syncthreads();                    // everyone done reading tile
    __nv_bfloat16* stg = (__nv_bfloat16*)tile;
    #pragma unroll
    for (int j = 0; j < 32; j++) stg[pl * 256 + dg + 8 * j] = __float2bfloat16(e[j] * sc);
    __syncthreads();
    // coalesced bf16 copy-out (as u32)
    const uint32_t* stg32 = (const uint32_t*)tile;
    uint32_t* dst = (uint32_t*)g_Zh;
    #pragma unroll 4
    for (int i = 0; i < 16; i++) {
        int idx = tid + (i << 8);
        int pl2 = idx >> 7, dw = idx & 127;
        int pp = pg * 32 + pl2;
        if (pp < P_) dst[((size_t)pp * N2 + b) * 128 + dw] = stg32[idx];
    }
}

// ---------------- attention weights (coalesced, single block) ----------------
__global__ __launch_bounds__(256) void k_wt(const float* __restrict__ att) {
    int t = threadIdx.x;
    if (t >= P_) return;
    float s = 0.0f;
    #pragma unroll 8
    for (int bc = 0; bc < B_ * 8; bc++) s += att[(size_t)bc * P_ + t];
    g_wt[t] = s;
}

// ---------------- main: bf16 mma.sync GEMM + exp + rowsum + diag dots --------
#define A_STRIDE 560            // bytes per A row (256 bf16 = 512B + 48 pad)
#define B_STRIDE 80             // bytes per B row (32 bf16 = 64B + 16 pad)
#define A_BYTES  (128 * A_STRIDE)          // 71680
#define B_CHUNK  (128 * B_STRIDE)          // 10240
#define SM_DYN   (A_BYTES + 2 * B_CHUNK)   // 92160

__global__ __launch_bounds__(256, 2) void k_main_mma() {
    extern __shared__ __align__(1024) char dynsm[];
    __shared__ float red[4][128];
    __shared__ float shred[32];

    uint32_t smA_u = s2u(dynsm);
    uint32_t smB_u = smA_u + A_BYTES;

    int tid  = threadIdx.x;
    int wid  = tid >> 5;
    int lane = tid & 31;
    int gq   = lane >> 2;       // group-of-4 id (row within 8)
    int t4   = lane & 3;
    int p    = blockIdx.y;
    int rt   = blockIdx.x;
    int r0   = rt << 7;
    int mwarp = wid & 1, nwarp = wid >> 1;
    int mbase = mwarp << 6;     // 0 or 64
    int nwbase = nwarp << 5;    // 0..96

    const __nv_bfloat16* Zh = g_Zh + (size_t)p * (N2 * D_);

    // per-lane ldmatrix offsets
    int q    = lane >> 3;
    int arow = ((q & 1) << 3) + (lane & 7);
    uint32_t aoff = (uint32_t)(arow * A_STRIDE + ((q >> 1) << 4));
    uint32_t boff = (uint32_t)(((((q >> 1) << 3) + (lane & 7)) * B_STRIDE) + ((q & 1) << 4));

    // ---- prologue: A resident (16 granules/thread) + B chunk 0, then B chunk 1
    #pragma unroll
    for (int i = 0; i < 16; i++) {
        int f4  = tid + (i << 8);
        int row = f4 >> 5, g16 = f4 & 31;
        const __nv_bfloat16* src = Zh + (size_t)(r0 + row) * D_ + g16 * 8;
        CPA16(smA_u + (uint32_t)(row * A_STRIDE + g16 * 16), src);
    }
    {   // B(ci=0): ct=0, kc=0
        #pragma unroll
        for (int i = 0; i < 2; i++) {
            int f4 = tid + (i << 8);
            int n = f4 >> 2, g4 = f4 & 3;
            const __nv_bfloat16* src = Zh + (size_t)n * D_ + g4 * 8;
            CPA16(smB_u + (uint32_t)(n * B_STRIDE + g4 * 16), src);
        }
    }
    CPA_COMMIT();
    {   // B(ci=1): ct=0, kc=1
        #pragma unroll
        for (int i = 0; i < 2; i++) {
            int f4 = tid + (i << 8);
            int n = f4 >> 2, g4 = f4 & 3;
            const __nv_bfloat16* src = Zh + (size_t)n * D_ + 32 + g4 * 8;
            CPA16(smB_u + (uint32_t)(B_CHUNK + n * B_STRIDE + g4 * 16), src);
        }
    }
    CPA_COMMIT();

    float acc[4][4][4];
    float rs_total = 0.0f;
    float dpart = 0.0f;

    #pragma unroll 1
    for (int ci = 0; ci < 64; ci++) {
        int kc = ci & 7, ct = ci >> 3;
        CPA_WAIT1();
        __syncthreads();
        if (kc == 0) {
            #pragma unroll
            for (int mb = 0; mb < 4; mb++)
                #pragma unroll
                for (int nb = 0; nb < 4; nb++)
                    #pragma unroll
                    for (int r = 0; r < 4; r++) acc[mb][nb][r] = 0.0f;
        }
        uint32_t bufb = smB_u + (uint32_t)((ci & 1) * B_CHUNK);
        #pragma unroll
        for (int kh = 0; kh < 2; kh++) {
            int kg = (kc << 1) + kh;
            uint32_t a[4][4];
            #pragma unroll
            for (int mb = 0; mb < 4; mb++) {
                uint32_t addr = smA_u + (uint32_t)((mbase + (mb << 4)) * A_STRIDE + (kg << 5)) + aoff;
                LDSM4(a[mb][0], a[mb][1], a[mb][2], a[mb][3], addr);
            }
            uint32_t bf[2][4];
            #pragma unroll
            for (int n2 = 0; n2 < 2; n2++) {
                uint32_t addr = bufb + (uint32_t)((nwbase + (n2 << 4)) * B_STRIDE + (kh << 5)) + boff;
                LDSM4(bf[n2][0], bf[n2][1], bf[n2][2], bf[n2][3], addr);
            }
            #pragma unroll
            for (int mb = 0; mb < 4; mb++) {
                MMA16816(acc[mb][0], a[mb], bf[0][0], bf[0][1]);
                MMA16816(acc[mb][1], a[mb], bf[0][2], bf[0][3]);
                MMA16816(acc[mb][2], a[mb], bf[1][0], bf[1][1]);
                MMA16816(acc[mb][3], a[mb], bf[1][2], bf[1][3]);
            }
        }
        if (kc == 7) {
            // ---- epilogue for col-tile ct ----
            bool isdiag = (ct == rt + 4);
            #pragma unroll
            for (int mb = 0; mb < 4; mb++) {
                int row0 = mbase + (mb << 4) + gq;
                float rs0 = 0.0f, rs1 = 0.0f;
                #pragma unroll
                for (int nb = 0; nb < 4; nb++) {
                    int col = nwbase + (nb << 3) + (t4 << 1);
                    float* c = acc[mb][nb];
                    rs0 += ex2f(c[0] * EXP_SCALE) + ex2f(c[1] * EXP_SCALE);
                    rs1 += ex2f(c[2] * EXP_SCALE) + ex2f(c[3] * EXP_SCALE);
                    if (isdiag) {
                        if (col == row0)          dpart += c[0];
                        else if (col + 1 == row0) dpart += c[1];
                        if (col == row0 + 8)          dpart += c[2];
                        else if (col + 1 == row0 + 8) dpart += c[3];
                    }
                }
                rs0 += __shfl_xor_sync(~0u, rs0, 1); rs0 += __shfl_xor_sync(~0u, rs0, 2);
                rs1 += __shfl_xor_sync(~0u, rs1, 1); rs1 += __shfl_xor_sync(~0u, rs1, 2);
                if (t4 == 0) { red[nwarp][row0] = rs0; red[nwarp][row0 + 8] = rs1; }
            }
            __syncthreads();
            if (tid < 128)
                rs_total += red[0][tid] + red[1][tid] + red[2][tid] + red[3][tid];
        }
        __syncthreads();     // all reads of buf (ci&1) and red done
        int cn = ci + 2;
        if (cn < 64) {
            int ctn = cn >> 3, kcn = cn & 7;
            uint32_t dstb = smB_u + (uint32_t)((cn & 1) * B_CHUNK);
            #pragma unroll
            for (int i = 0; i < 2; i++) {
                int f4 = tid + (i << 8);
                int n = f4 >> 2, g4 = f4 & 3;
                const __nv_bfloat16* src = Zh + (size_t)(ctn * 128 + n) * D_ + kcn * 32 + g4 * 8;
                CPA16(dstb + (uint32_t)(n * B_STRIDE + g4 * 16), src);
            }
        }
        CPA_COMMIT();        // always commit so group counting stays uniform
    }

    if (tid < 128) g_S[p * N2 + r0 + tid] = rs_total;

    float dp = blockSum256(dpart, shred);
    if (tid == 0 && rt < 4) g_dsum4[p * 4 + rt] = dp;
}

// ---------------- per-position loss ----------------
__global__ __launch_bounds__(256) void k_final() {
    int p = blockIdx.x;
    __shared__ float sh[32];
    float acc = 0.0f;
    for (int r = threadIdx.x; r < N2; r += 256) {
        float self = ex2f(g_rn2[p * N2 + r] * EXP_SCALE);   // exp(sim_rr)
        acc += logf(g_S[p * N2 + r] - self);
    }
    acc = blockSum256(acc, sh);
    if (threadIdx.x == 0) {
        float dsum = g_dsum4[p * 4] + g_dsum4[p * 4 + 1] +
                     g_dsum4[p * 4 + 2] + g_dsum4[p * 4 + 3];
        g_ploss[p] = (acc - 4.0f * dsum) * g_wt[p] *
                     (1.0f / ((float)N2 * (float)B_ * (float)P_));
    }
}

// ---------------- final scalar ----------------
__global__ __launch_bounds__(256) void k_out(float* out, int n) {
    __shared__ float sh[32];
    int t = threadIdx.x;
    for (int i = t; i < n; i += 256) out[i] = 0.0f;
    float v = (t < P_) ? g_ploss[t] : 0.0f;
    v = blockSum256(v, sh);
    if (t == 0) out[0] = v;
}

// ---------------- launch ----------------
extern "C" void kernel_launch(void* const* d_in, const int* in_sizes, int n_in,
                              void* d_out, int out_size) {
    const float* gf = nullptr; const float* att = nullptr; const float* outp = nullptr;
    for (int i = 0; i < n_in; i++) {
        if (in_sizes[i] == B_ * D_)            gf   = (const float*)d_in[i];
        else if (in_sizes[i] == B_ * 8 * P_)   att  = (const float*)d_in[i];
        else if (in_sizes[i] == B_ * D_ * P_)  outp = (const float*)d_in[i];
    }
    if (!gf)   gf   = (const float*)d_in[0];
    if (!att)  att  = (const float*)d_in[1];
    if (!outp) outp = (const float*)d_in[2];

    cudaFuncSetAttribute(k_main_mma, cudaFuncAttributeMaxDynamicSharedMemorySize, SM_DYN);

    k_buildG<<<B_, 32>>>(gf);
    k_buildA<<<dim3(7, B_), 256>>>(outp);
    k_wt<<<1, 256>>>(att);
    k_main_mma<<<dim3(8, P_), 256, SM_DYN>>>();
    k_final<<<P_, 256>>>();
    k_out<<<1, 256>>>((float*)d_out, out_size);
}

// round 5
// speedup vs baseline: 7.5150x; 1.7032x over previous
#include <cuda_runtime.h>
#include <cuda_bf16.h>
#include <cstdint>

#define B_ 512
#define D_ 256
#define P_ 196
#define N2 1024   // 2*B

// exp(dot / T) with T=0.5 -> exp2(dot * 2*log2(e))
#define EXP_SCALE 2.8853900817779268f
#define LOG2E     1.4426950408889634f
#define LN2F      0.6931471805599453f

// ---------------- device scratch (no allocations allowed) ----------------
__device__ __nv_bfloat16 g_Zh[(size_t)P_ * N2 * D_];  // [p][row][d] bf16; rows 0..511 local, 512..1023 G chain
__device__ float g_S[P_ * N2];      // per-row sums of exp(sim)
__device__ float g_rn2[P_ * N2];    // per-row |z|^2 (diag correction)
__device__ float g_wtp[32 * P_];    // attention-sum partials (32 row-groups)
__device__ float g_dsum4[P_ * 4];   // partial positive-pair dots (per row-tile rt<4)
__device__ float g_ploss[P_];       // per-position loss

// ---------------- small helpers ----------------
__device__ __forceinline__ float ex2f(float x) {
    float y; asm("ex2.approx.f32 %0, %1;" : "=f"(y) : "f"(x)); return y;
}
__device__ __forceinline__ float lg2f(float x) {
    float y; asm("lg2.approx.f32 %0, %1;" : "=f"(y) : "f"(x)); return y;
}
__device__ __forceinline__ unsigned s2u(const void* p) {
    return (unsigned)__cvta_generic_to_shared(p);
}
__device__ __forceinline__ float warpSum(float v) {
    #pragma unroll
    for (int o = 16; o > 0; o >>= 1) v += __shfl_xor_sync(0xffffffffu, v, o);
    return v;
}
__device__ __forceinline__ float blockSum256(float v, float* sh) {
    int w = threadIdx.x >> 5, l = threadIdx.x & 31;
    v = warpSum(v);
    __syncthreads();
    if (l == 0) sh[w] = v;
    __syncthreads();
    if (w == 0) {
        float x = (l < 8) ? sh[l] : 0.0f;
        x = warpSum(x);
        if (l == 0) sh[0] = x;
    }
    __syncthreads();
    return sh[0];
}

#define CPA16(dst_, src_) \
    asm volatile("cp.async.cg.shared.global [%0], [%1], 16;" :: "r"(dst_), "l"(src_))
#define CPA_COMMIT() asm volatile("cp.async.commit_group;" ::: "memory")
#define CPA_WAITG1() asm volatile("cp.async.wait_group 1;"  ::: "memory")

#define LDSM4(r0_, r1_, r2_, r3_, addr_) \
    asm volatile("ldmatrix.sync.aligned.m8n8.x4.shared.b16 {%0,%1,%2,%3}, [%4];" \
        : "=r"(r0_), "=r"(r1_), "=r"(r2_), "=r"(r3_) : "r"(addr_))

#define MMA16816(c_, a_, b0_, b1_) \
    asm volatile("mma.sync.aligned.m16n8k16.row.col.f32.bf16.bf16.f32 " \
        "{%0,%1,%2,%3}, {%4,%5,%6,%7}, {%8,%9}, {%0,%1,%2,%3};" \
        : "+f"((c_)[0]), "+f"((c_)[1]), "+f"((c_)[2]), "+f"((c_)[3]) \
        : "r"((a_)[0]), "r"((a_)[1]), "r"((a_)[2]), "r"((a_)[3]), "r"(b0_), "r"(b1_))

// ---------------- stage 1: global-feature softmax chain (1 warp / row) ------
// No max-shift (softmax is shift-invariant; inputs bounded): shorter chain.
__global__ __launch_bounds__(32) void k_buildG(const float* __restrict__ gf) {
    int b = blockIdx.x;
    int lane = threadIdx.x;
    float v[8];
    #pragma unroll
    for (int j = 0; j < 8; j++) v[j] = gf[b * D_ + j * 32 + lane];
    for (int p = 0; p < P_; p++) {
        float e[8], s = 0.0f, s2 = 0.0f;
        #pragma unroll
        for (int j = 0; j < 8; j++) {
            e[j] = ex2f(v[j] * LOG2E);
            s  += e[j];
            s2 += e[j] * e[j];
        }
        // interleaved reductions (two independent shfl chains pipeline)
        #pragma unroll
        for (int o = 16; o > 0; o >>= 1) {
            s  += __shfl_xor_sync(~0u, s,  o);
            s2 += __shfl_xor_sync(~0u, s2, o);
        }
        float inv_s = 1.0f / s;
        float q = s2 * inv_s * inv_s;               // |softmax|^2
        float inv = 1.0f / (sqrtf(q) + 1e-8f);
        float sc = inv_s * inv;
        #pragma unroll
        for (int j = 0; j < 8; j++) {
            g_Zh[((size_t)p * N2 + B_ + b) * D_ + j * 32 + lane] =
                __float2bfloat16(e[j] * sc);
            v[j] = e[j] * inv_s;                    // carry softmax output
        }
        if (lane == 0) g_rn2[p * N2 + B_ + b] = q * inv * inv;
    }
}

// ---------------- stage 2: local-feature softmax (coalesced, 32 p per block)
__global__ __launch_bounds__(256) void k_buildA(const float* __restrict__ outp) {
    __shared__ float tile[32 * 264];     // [p_local][d] stride 264
    int pg = blockIdx.x, b = blockIdx.y;
    int tid = threadIdx.x;
    #pragma unroll 4
    for (int i = 0; i < 32; i++) {
        int idx = tid + (i << 8);
        int pl = idx & 31, d = idx >> 5;
        int p = pg * 32 + pl;
        float x = (p < P_) ? outp[((size_t)b * D_ + d) * P_ + p] : 0.0f;
        tile[pl * 264 + d] = x;
    }
    __syncthreads();
    int dg = tid & 7, pl = tid >> 3;
    int p  = pg * 32 + pl;
    float x[32];
    #pragma unroll
    for (int j = 0; j < 32; j++) x[j] = tile[pl * 264 + dg + 8 * j];
    float e[32], s = 0.0f, s2 = 0.0f;
    #pragma unroll
    for (int j = 0; j < 32; j++) {
        e[j] = ex2f(x[j] * LOG2E);
        s += e[j]; s2 += e[j] * e[j];
    }
    s  += __shfl_xor_sync(~0u, s, 1);  s  += __shfl_xor_sync(~0u, s, 2);  s  += __shfl_xor_sync(~0u, s, 4);
    s2 += __shfl_xor_sync(~0u, s2, 1); s2 += __shfl_xor_sync(~0u, s2, 2); s2 += __shfl_xor_sync(~0u, s2, 4);
    float inv_s = 1.0f / s;
    float q = s2 * inv_s * inv_s;
    float inv = 1.0f / (sqrtf(q) + 1e-8f);
    float sc = inv_s * inv;
    if (dg == 0 && p < P_) g_rn2[p * N2 + b] = q * inv * inv;
    __syncthreads();
    __nv_bfloat16* stg = (__nv_bfloat16*)tile;
    #pragma unroll
    for (int j = 0; j < 32; j++) stg[pl * 256 + dg + 8 * j] = __float2bfloat16(e[j] * sc);
    __syncthreads();
    const uint32_t* stg32 = (const uint32_t*)tile;
    uint32_t* dst = (uint32_t*)g_Zh;
    #pragma unroll 4
    for (int i = 0; i < 16; i++) {
        int idx = tid + (i << 8);
        int pl2 = idx >> 7, dw = idx & 127;
        int pp = pg * 32 + pl2;
        if (pp < P_) dst[((size_t)pp * N2 + b) * 128 + dw] = stg32[idx];
    }
}

// ---------------- attention weights: 32 coalesced partial blocks -------------
__global__ __launch_bounds__(256) void k_wt(const float* __restrict__ att) {
    int t = threadIdx.x;
    int g = blockIdx.x;               // 32 blocks, 128 rows each
    if (t >= P_) return;
    const float* base = att + (size_t)(g * 128) * P_ + t;
    float s = 0.0f;
    #pragma unroll 8
    for (int r = 0; r < 128; r++) s += base[(size_t)r * P_];
    g_wtp[g * P_ + t] = s;
}

// ---------------- main: bf16 mma.sync GEMM + exp + rowsum + diag dots --------
#define A_STRIDE 560            // bytes per A row (256 bf16 = 512B + 48 pad)
#define B_STRIDE 80             // bytes per B row (32 bf16 = 64B + 16 pad)
#define A_BYTES  (128 * A_STRIDE)          // 71680
#define B_CHUNK  (128 * B_STRIDE)          // 10240
#define NSTAGE   3
#define SM_DYN   (A_BYTES + NSTAGE * B_CHUNK)   // 102400

__global__ __launch_bounds__(256, 2) void k_main_mma() {
    extern __shared__ __align__(1024) char dynsm[];
    __shared__ float shred[32];

    uint32_t smA_u = s2u(dynsm);
    uint32_t smB_u = smA_u + A_BYTES;

    int tid  = threadIdx.x;
    int wid  = tid >> 5;
    int lane = tid & 31;
    int gq   = lane >> 2;       // row-within-8
    int t4   = lane & 3;
    int p    = blockIdx.y;
    int rt   = blockIdx.x;
    int r0   = rt << 7;
    int mwarp = wid & 1, nwarp = wid >> 1;
    int mbase = mwarp << 6;     // 0 or 64
    int nwbase = nwarp << 5;    // 0..96

    const __nv_bfloat16* Zh = g_Zh + (size_t)p * (N2 * D_);

    // per-lane ldmatrix offsets
    int q    = lane >> 3;
    int arow = ((q & 1) << 3) + (lane & 7);
    uint32_t aoff = (uint32_t)(arow * A_STRIDE + ((q >> 1) << 4));
    uint32_t boff = (uint32_t)(((((q >> 1) << 3) + (lane & 7)) * B_STRIDE) + ((q & 1) << 4));

    // ---- prologue: A resident + B stages 0,1 ----
    #pragma unroll
    for (int i = 0; i < 16; i++) {
        int f4  = tid + (i << 8);
        int row = f4 >> 5, g16 = f4 & 31;
        CPA16(smA_u + (uint32_t)(row * A_STRIDE + g16 * 16),
              Zh + (size_t)(r0 + row) * D_ + g16 * 8);
    }
    #pragma unroll
    for (int i = 0; i < 2; i++) {      // B stage 0 = (ct0,kc0)
        int f4 = tid + (i << 8);
        int n = f4 >> 2, g4 = f4 & 3;
        CPA16(smB_u + (uint32_t)(n * B_STRIDE + g4 * 16),
              Zh + (size_t)n * D_ + g4 * 8);
    }
    CPA_COMMIT();
    #pragma unroll
    for (int i = 0; i < 2; i++) {      // B stage 1 = (ct0,kc1)
        int f4 = tid + (i << 8);
        int n = f4 >> 2, g4 = f4 & 3;
        CPA16(smB_u + (uint32_t)(B_CHUNK + n * B_STRIDE + g4 * 16),
              Zh + (size_t)n * D_ + 32 + g4 * 8);
    }
    CPA_COMMIT();

    float acc[4][4][4];
    float rs_reg[8];
    #pragma unroll
    for (int i = 0; i < 8; i++) rs_reg[i] = 0.0f;
    float dpart = 0.0f;

    int stage = 0;
    #pragma unroll 1
    for (int ci = 0; ci < 64; ci++) {
        int kc = ci & 7, ct = ci >> 3;
        CPA_WAITG1();                  // stage `stage` ready
        __syncthreads();               // visible to all; old reads of next-write stage done
        // prefetch stage for ci+2
        int cn = ci + 2;
        if (cn < 64) {
            int ctn = cn >> 3, kcn = cn & 7;
            int sn = cn % NSTAGE;
            uint32_t dstb = smB_u + (uint32_t)(sn * B_CHUNK);
            #pragma unroll
            for (int i = 0; i < 2; i++) {
                int f4 = tid + (i << 8);
                int n = f4 >> 2, g4 = f4 & 3;
                CPA16(dstb + (uint32_t)(n * B_STRIDE + g4 * 16),
                      Zh + (size_t)(ctn * 128 + n) * D_ + kcn * 32 + g4 * 8);
            }
        }
        CPA_COMMIT();

        if (kc == 0) {
            #pragma unroll
            for (int mb = 0; mb < 4; mb++)
                #pragma unroll
                for (int nb = 0; nb < 4; nb++)
                    #pragma unroll
                    for (int r = 0; r < 4; r++) acc[mb][nb][r] = 0.0f;
        }
        uint32_t bufb = smB_u + (uint32_t)(stage * B_CHUNK);
        #pragma unroll
        for (int kh = 0; kh < 2; kh++) {
            int kg = (kc << 1) + kh;
            uint32_t a[4][4];
            #pragma unroll
            for (int mb = 0; mb < 4; mb++) {
                uint32_t addr = smA_u + (uint32_t)((mbase + (mb << 4)) * A_STRIDE + (kg << 5)) + aoff;
                LDSM4(a[mb][0], a[mb][1], a[mb][2], a[mb][3], addr);
            }
            uint32_t bf[2][4];
            #pragma unroll
            for (int n2 = 0; n2 < 2; n2++) {
                uint32_t addr = bufb + (uint32_t)((nwbase + (n2 << 4)) * B_STRIDE + (kh << 5)) + boff;
                LDSM4(bf[n2][0], bf[n2][1], bf[n2][2], bf[n2][3], addr);
            }
            #pragma unroll
            for (int mb = 0; mb < 4; mb++) {
                MMA16816(acc[mb][0], a[mb], bf[0][0], bf[0][1]);
                MMA16816(acc[mb][1], a[mb], bf[0][2], bf[0][3]);
                MMA16816(acc[mb][2], a[mb], bf[1][0], bf[1][1]);
                MMA16816(acc[mb][3], a[mb], bf[1][2], bf[1][3]);
            }
        }
        if (kc == 7) {
            // register-only epilogue for this col-tile
            bool isdiag = (ct == rt + 4);
            #pragma unroll
            for (int mb = 0; mb < 4; mb++) {
                int row0 = mbase + (mb << 4) + gq;
                float rs0 = 0.0f, rs1 = 0.0f;
                #pragma unroll
                for (int nb = 0; nb < 4; nb++) {
                    int col = nwbase + (nb << 3) + (t4 << 1);
                    float* c = acc[mb][nb];
                    rs0 += ex2f(c[0] * EXP_SCALE) + ex2f(c[1] * EXP_SCALE);
                    rs1 += ex2f(c[2] * EXP_SCALE) + ex2f(c[3] * EXP_SCALE);
                    if (isdiag) {
                        if (col == row0)          dpart += c[0];
                        else if (col + 1 == row0) dpart += c[1];
                        if (col == row0 + 8)          dpart += c[2];
                        else if (col + 1 == row0 + 8) dpart += c[3];
                    }
                }
                rs_reg[mb * 2 + 0] += rs0;
                rs_reg[mb * 2 + 1] += rs1;
            }
        }
        stage++; if (stage == NSTAGE) stage = 0;
    }

    // ---- final combine: t4-shfl, then cross-warp via reused A smem ----
    __syncthreads();                        // all smem reads done; safe to reuse
    #pragma unroll
    for (int i = 0; i < 8; i++) {
        rs_reg[i] += __shfl_xor_sync(~0u, rs_reg[i], 1);
        rs_reg[i] += __shfl_xor_sync(~0u, rs_reg[i], 2);
    }
    float* red = (float*)dynsm;             // 4*128 floats used
    if (t4 == 0) {
        #pragma unroll
        for (int mb = 0; mb < 4; mb++) {
            int row0 = mbase + (mb << 4) + gq;
            red[nwarp * 128 + row0]     = rs_reg[mb * 2 + 0];
            red[nwarp * 128 + row0 + 8] = rs_reg[mb * 2 + 1];
        }
    }
    __syncthreads();
    if (tid < 128)
        g_S[p * N2 + r0 + tid] = red[tid] + red[128 + tid] + red[256 + tid] + red[384 + tid];

    float dp = blockSum256(dpart, shred);
    if (tid == 0 && rt < 4) g_dsum4[p * 4 + rt] = dp;
}

// ---------------- per-position loss ----------------
__global__ __launch_bounds__(256) void k_final() {
    int p = blockIdx.x;
    __shared__ float sh[32];
    float acc = 0.0f;
    for (int r = threadIdx.x; r < N2; r += 256) {
        float self = ex2f(g_rn2[p * N2 + r] * EXP_SCALE);   // exp(sim_rr)
        acc += lg2f(g_S[p * N2 + r] - self);
    }
    acc = blockSum256(acc, sh) * LN2F;
    if (threadIdx.x == 0) {
        float wt = 0.0f;
        #pragma unroll
        for (int g = 0; g < 32; g++) wt += g_wtp[g * P_ + p];
        float dsum = g_dsum4[p * 4] + g_dsum4[p * 4 + 1] +
                     g_dsum4[p * 4 + 2] + g_dsum4[p * 4 + 3];
        g_ploss[p] = (acc - 4.0f * dsum) * wt *
                     (1.0f / ((float)N2 * (float)B_ * (float)P_));
    }
}

// ---------------- final scalar ----------------
__global__ __launch_bounds__(256) void k_out(float* out, int n) {
    __shared__ float sh[32];
    int t = threadIdx.x;
    for (int i = t; i < n; i += 256) out[i] = 0.0f;
    float v = (t < P_) ? g_ploss[t] : 0.0f;
    v = blockSum256(v, sh);
    if (t == 0) out[0] = v;
}

// ---------------- launch ----------------
extern "C" void kernel_launch(void* const* d_in, const int* in_sizes, int n_in,
                              void* d_out, int out_size) {
    const float* gf = nullptr; const float* att = nullptr; const float* outp = nullptr;
    for (int i = 0; i < n_in; i++) {
        if (in_sizes[i] == B_ * D_)            gf   = (const float*)d_in[i];
        else if (in_sizes[i] == B_ * 8 * P_)   att  = (const float*)d_in[i];
        else if (in_sizes[i] == B_ * D_ * P_)  outp = (const float*)d_in[i];
    }
    if (!gf)   gf   = (const float*)d_in[0];
    if (!att)  att  = (const float*)d_in[1];
    if (!outp) outp = (const float*)d_in[2];

    cudaFuncSetAttribute(k_main_mma, cudaFuncAttributeMaxDynamicSharedMemorySize, SM_DYN);

    k_buildG<<<B_, 32>>>(gf);
    k_buildA<<<dim3(7, B_), 256>>>(outp);
    k_wt<<<32, 256>>>(att);
    k_main_mma<<<dim3(8, P_), 256, SM_DYN>>>();
    k_final<<<P_, 256>>>();
    k_out<<<1, 256>>>((float*)d_out, out_size);
}